// round 16
// baseline (speedup 1.0000x reference)
#include <cuda_runtime.h>
#include <cuda_fp16.h>
#include <math.h>
#include <stdint.h>

// ---------------- problem constants ----------------
#define DIMC   2048
#define SEQ    2048
#define BATCH  2
#define HEADS  16
#define DH     128
#define FFI    8192
#define NPROJ  18688            // 2048+128+128+8192+8192
#define NROWS  4096             // BATCH*SEQ
#define NCAT   10240            // 2048 (attn) + 8192 (ff)
#define RMS_SCALE 45.25483399593904f   // sqrt(2048)
#define Q_SCALE   0.08838834764831845f // 1/sqrt(128)
#define LOG2E     1.4426950408889634f

// gemm smem (tile 128x64, K-chunk 32): A 128x80=10240, B 64x80=5120
// 3 stages * 15360 = 46080 -> 3 CTAs/SM = 138 KB
#define TILE_A_B 10240
#define STAGE_B  15360
#define SMEM_GEMM 46080
// flash smem: 2 stages * (K 128x272 + V 144x272) = 147968
#define FSTRIDE  272
#define FK_TILE  34816
#define FSTAGE   73984
#define SMEM_FLASH 147968

// ---------------- scratch (device globals; allocation-free) ----------------
__device__ __half g_xn  [(size_t)NROWS * DIMC];
__device__ __half g_wiT [(size_t)NPROJ * DIMC];     // PERMUTED: q|k|v|ff/gate interleaved
__device__ __half g_qt  [(size_t)BATCH * HEADS * SEQ * DH];
__device__ __half g_kt  [(size_t)BATCH * SEQ * DH];
__device__ __half g_vt  [(size_t)BATCH * DH * SEQ];
__device__ __half g_cat [(size_t)NROWS * NCAT];     // [at | h]
__device__ __half g_wcat[(size_t)DIMC * NCAT];      // [awT | fwT]

// ---------------- helpers ----------------
__device__ __forceinline__ uint32_t smem_u32(const void* p) {
    uint32_t a;
    asm("{ .reg .u64 t; cvta.to.shared.u64 t, %1; cvt.u32.u64 %0, t; }"
        : "=r"(a) : "l"(p));
    return a;
}
__device__ __forceinline__ void ldm4(uint32_t* r, uint32_t a) {
    asm volatile("ldmatrix.sync.aligned.m8n8.x4.shared.b16 {%0,%1,%2,%3}, [%4];"
                 : "=r"(r[0]), "=r"(r[1]), "=r"(r[2]), "=r"(r[3]) : "r"(a));
}
__device__ __forceinline__ void mma16816(float* d, const uint32_t* a,
                                         uint32_t b0, uint32_t b1) {
    asm volatile(
        "mma.sync.aligned.m16n8k16.row.col.f32.f16.f16.f32 "
        "{%0,%1,%2,%3}, {%4,%5,%6,%7}, {%8,%9}, {%0,%1,%2,%3};"
        : "+f"(d[0]), "+f"(d[1]), "+f"(d[2]), "+f"(d[3])
        : "r"(a[0]), "r"(a[1]), "r"(a[2]), "r"(a[3]), "r"(b0), "r"(b1));
}
__device__ __forceinline__ void cp16(uint32_t s, const void* g) {
    asm volatile("cp.async.cg.shared.global [%0], [%1], 16;" :: "r"(s), "l"(g));
}
#define CP_COMMIT() asm volatile("cp.async.commit_group;")
#define CP_WAITG1() asm volatile("cp.async.wait_group 1;" ::: "memory")
__device__ __forceinline__ uint32_t pack2(float v0, float v1) {
    __half2 H = __floats2half2_rn(v0, v1);
    return *(uint32_t*)&H;
}
__device__ __forceinline__ uint32_t exp2h2(float v0, float v1) {
    uint32_t p = pack2(v0, v1), r;
    asm("ex2.approx.f16x2 %0, %1;" : "=r"(r) : "r"(p));
    return r;
}

// ====== GEMM mainloop: tile 128x64, K-chunk 32, 3-stage, 3 CTAs/SM ======
// 8 warps: mw = wid&3 (32 rows each), nw = wid>>2 (32 cols each).
#define GEMM_ISSUE(cidx, Aptr, lda_, Bptr, ldb_)                                        \
    {                                                                                   \
        const int k0i = (cidx) << 5;                                                    \
        const uint32_t db = sb + ((cidx) % 3) * STAGE_B;                                \
        _Pragma("unroll")                                                               \
        for (int qq = 0; qq < 2; qq++) {                                                \
            const int lin = qq * 256 + tid;                                             \
            const int rr = lin >> 2, ss = lin & 3;                                      \
            cp16(db + rr*80 + ss*16,                                                    \
                 (Aptr) + (size_t)(row0 + rr) * (lda_) + k0i + ss*8);                   \
        }                                                                               \
        {                                                                               \
            const int rr = tid >> 2, ss = tid & 3;                                      \
            cp16(db + TILE_A_B + rr*80 + ss*16,                                         \
                 (Bptr) + (size_t)(col0 + rr) * (ldb_) + k0i + ss*8);                   \
        }                                                                               \
    }

#define GEMM_MAIN(Aptr, lda_, Bptr, ldb_, Kdim)                                         \
    float acc[2][4][4];                                                                 \
    _Pragma("unroll")                                                                   \
    for (int i = 0; i < 2; i++)                                                         \
        _Pragma("unroll")                                                               \
        for (int j = 0; j < 4; j++)                                                     \
            _Pragma("unroll")                                                           \
            for (int k = 0; k < 4; k++) acc[i][j][k] = 0.f;                             \
    const int NC = (Kdim) >> 5;                                                         \
    const int lrow = lane & 15;                                                         \
    const int lchk = lane >> 4;                                                         \
    GEMM_ISSUE(0, Aptr, lda_, Bptr, ldb_); CP_COMMIT();                                 \
    GEMM_ISSUE(1, Aptr, lda_, Bptr, ldb_); CP_COMMIT();                                 \
    for (int c = 0; c < NC; c++) {                                                      \
        CP_WAITG1();                       /* chunk c resident */                       \
        __syncthreads();                   /* prev compute drained */                   \
        if (c + 2 < NC) GEMM_ISSUE(c + 2, Aptr, lda_, Bptr, ldb_);                      \
        CP_COMMIT();                                                                    \
        const uint32_t tb = sb + (c % 3) * STAGE_B;                                     \
        _Pragma("unroll")                                                               \
        for (int kk = 0; kk < 2; kk++) {                                                \
            const int ch0 = kk * 2;                                                     \
            uint32_t aF[2][4], bF[2][4];                                                \
            _Pragma("unroll")                                                           \
            for (int mt = 0; mt < 2; mt++)                                              \
                ldm4(aF[mt], tb + (mw*32 + mt*16 + lrow)*80 + (ch0 + lchk)*16);         \
            _Pragma("unroll")                                                           \
            for (int nt = 0; nt < 2; nt++)                                              \
                ldm4(bF[nt], tb + TILE_A_B + (nw*32 + nt*16 + lrow)*80 + (ch0 + lchk)*16);\
            _Pragma("unroll")                                                           \
            for (int mt = 0; mt < 2; mt++) {                                            \
                _Pragma("unroll")                                                       \
                for (int n8 = 0; n8 < 4; n8++) {                                        \
                    const int g = n8 >> 1, p = n8 & 1;                                  \
                    mma16816(acc[mt][n8], aF[mt], bF[g][p], bF[g][p + 2]);              \
                }                                                                       \
            }                                                                           \
        }                                                                               \
    }

// ---------------- plain GEMM (final output) ----------------
__global__ __launch_bounds__(256, 3) void gemm_kernel(
    const __half* __restrict__ A, int lda,
    const __half* __restrict__ B, int ldb,
    float* __restrict__ C, int ldc, int K)
{
    extern __shared__ char smem[];
    const uint32_t sb = smem_u32(smem);
    const int tid  = threadIdx.x;
    const int wid  = tid >> 5;
    const int lane = tid & 31;
    const int mw   = wid & 3;
    const int nw   = wid >> 2;
    const int row0 = blockIdx.x * 128, col0 = blockIdx.y * 64;

    GEMM_MAIN(A, lda, B, ldb, K)

    const int tr  = lane >> 2;
    const int tc2 = (lane & 3) * 2;
    #pragma unroll
    for (int mt = 0; mt < 2; mt++)
        #pragma unroll
        for (int hf = 0; hf < 2; hf++) {
            const int r = row0 + mw*32 + mt*16 + hf*8 + tr;
            #pragma unroll
            for (int n8 = 0; n8 < 4; n8++) {
                const int cc = col0 + nw*32 + n8*8 + tc2;
                float* cp = C + (size_t)r * ldc + cc;
                cp[0] = acc[mt][n8][hf*2 + 0];
                cp[1] = acc[mt][n8][hf*2 + 1];
            }
        }
}

// ---------------- proj GEMM with fused gather epilogue ----------------
// B = permuted wiT: rows 0..2047 q, 2048..2175 k, 2176..2303 v,
//                   2304..18687 interleaved (even=ff_j, odd=gate_j).
// Region boundaries (2048, 2176, 2304) are multiples of 64 -> col0 dispatch ok.
__global__ __launch_bounds__(256, 3) void proj_kernel(
    const __half* __restrict__ A, int lda,
    const __half* __restrict__ B, int ldb,
    __half* __restrict__ q, __half* __restrict__ kmat,
    __half* __restrict__ vmat, __half* __restrict__ cat, int K)
{
    extern __shared__ char smem[];
    const uint32_t sb = smem_u32(smem);
    const int tid  = threadIdx.x;
    const int wid  = tid >> 5;
    const int lane = tid & 31;
    const int mw   = wid & 3;
    const int nw   = wid >> 2;
    const int row0 = blockIdx.x * 128, col0 = blockIdx.y * 64;

    GEMM_MAIN(A, lda, B, ldb, K)

    const int tr  = lane >> 2;
    const int tc2 = (lane & 3) * 2;

    #pragma unroll
    for (int mt = 0; mt < 2; mt++)
        #pragma unroll
        for (int hf = 0; hf < 2; hf++) {
            const int r = row0 + mw*32 + mt*16 + hf*8 + tr;
            const int i = r & 2047, b = r >> 11;
            #pragma unroll
            for (int n8 = 0; n8 < 4; n8++) {
                const int cc = col0 + nw*32 + n8*8 + tc2;
                const float v0 = acc[mt][n8][hf*2 + 0];
                const float v1 = acc[mt][n8][hf*2 + 1];
                if (col0 < 2048) {
                    // q[z][i][d], pre-scaled by Q_SCALE*LOG2E
                    const int h = cc >> 7, d = cc & 127;
                    const size_t o = ((size_t)(b * HEADS + h) * SEQ + i) * DH + d;
                    *(uint32_t*)(q + o) = pack2(v0 * (Q_SCALE * LOG2E),
                                                v1 * (Q_SCALE * LOG2E));
                } else if (col0 < 2176) {
                    // k[b][j][d]
                    const int d = cc - 2048;
                    *(uint32_t*)(kmat + (size_t)r * DH + d) = pack2(v0, v1);
                } else if (col0 < 2304) {
                    // v[b][d][j]: scattered transpose (small region)
                    const int d = cc - 2176;
                    const size_t o = (size_t)b * DH * SEQ + (size_t)d * SEQ + i;
                    vmat[o]       = __float2half_rn(v0);
                    vmat[o + SEQ] = __float2half_rn(v1);
                } else {
                    // interleaved ff/gate: v0 = ff_j, v1 = gate_j
                    const int jp = (cc - 2304) >> 1;
                    const float sw = v1 / (1.f + __expf(-v1));
                    cat[(size_t)r * NCAT + 2048 + jp] = __float2half_rn(v0 * sw);
                }
            }
        }
}

// ---------------- fused flash attention ----------------
__global__ __launch_bounds__(256) void flash_kernel(
    const __half* __restrict__ q,      // [z][i][dh]  (pre-scaled by Q_SCALE*log2e)
    const __half* __restrict__ kmat,   // [b][key][dh]
    const __half* __restrict__ vmat,   // [b][dh][key]
    const float* __restrict__ bias,    // [h][i][j]
    __half* __restrict__ at, int ldo)
{
    extern __shared__ char smem[];
    const uint32_t sb = smem_u32(smem);
    const int tid  = threadIdx.x;
    const int wid  = tid >> 5;
    const int lane = tid & 31;
    const int gr   = lane >> 2;
    const int tc   = lane & 3;
    const int lrow = lane & 15;
    const int lchk = lane >> 4;

    const int z = blockIdx.y, b = z >> 4, h = z & 15;
    const int r0 = blockIdx.x * 128 + wid * 16;

    // init ones-row (dh=128) and zero rows of both V buffers
    #pragma unroll
    for (int bufi = 0; bufi < 2; bufi++) {
        char* vrows = smem + bufi * FSTAGE + FK_TILE + 128 * FSTRIDE;
        for (int i = tid; i < 16 * 136; i += 256) {
            const int r = i / 136, cc = i % 136;
            *(__half*)(vrows + r * FSTRIDE + cc * 2) =
                (r == 0) ? __float2half(1.0f) : __float2half(0.0f);
        }
    }

    uint32_t qF[8][4];
    {
        const __half* qb = q + (size_t)z * SEQ * DH;
        #pragma unroll
        for (int kt = 0; kt < 8; kt++) {
            const int c0 = kt * 16 + 2 * tc;
            qF[kt][0] = *(const uint32_t*)(qb + (size_t)(r0 + gr    ) * DH + c0);
            qF[kt][1] = *(const uint32_t*)(qb + (size_t)(r0 + gr + 8) * DH + c0);
            qF[kt][2] = *(const uint32_t*)(qb + (size_t)(r0 + gr    ) * DH + c0 + 8);
            qF[kt][3] = *(const uint32_t*)(qb + (size_t)(r0 + gr + 8) * DH + c0 + 8);
        }
    }

    const __half* ksrc = kmat + (size_t)b * SEQ * DH;
    const __half* vsrc = vmat + (size_t)b * DH * SEQ;

    auto issueKV = [&](int j, int buf) {
        const uint32_t kb = sb + buf * FSTAGE;
        #pragma unroll
        for (int t = 0; t < 8; t++) {
            const int lin = t * 256 + tid;
            const int r = lin >> 4, s = lin & 15;
            cp16(kb + r * FSTRIDE + s * 16,
                 ksrc + (size_t)(j * 128 + r) * DH + s * 8);
            cp16(kb + FK_TILE + r * FSTRIDE + s * 16,
                 vsrc + (size_t)r * SEQ + j * 128 + s * 8);
        }
    };

    issueKV(0, 0);
    CP_COMMIT();

    float Oacc[17][4];
    #pragma unroll
    for (int i = 0; i < 17; i++)
        #pragma unroll
        for (int k = 0; k < 4; k++) Oacc[i][k] = 0.f;

    for (int j = 0; j < 16; j++) {
        const int buf = j & 1;
        __syncthreads();
        if (j + 1 < 16) issueKV(j + 1, buf ^ 1);
        CP_COMMIT();
        CP_WAITG1();
        __syncthreads();

        const uint32_t kb = sb + buf * FSTAGE;
        const uint32_t vb = kb + FK_TILE;

        float S[16][4];
        #pragma unroll
        for (int i = 0; i < 16; i++)
            #pragma unroll
            for (int k = 0; k < 4; k++) S[i][k] = 0.f;

        #pragma unroll
        for (int kt = 0; kt < 8; kt++) {
            uint32_t bK[8][4];
            #pragma unroll
            for (int nt = 0; nt < 8; nt++)
                ldm4(bK[nt], kb + (nt * 16 + lrow) * FSTRIDE + kt * 32 + lchk * 16);
            #pragma unroll
            for (int n8 = 0; n8 < 16; n8++) {
                const int g = n8 >> 1, p = n8 & 1;
                mma16816(S[n8], qF[kt], bK[g][p], bK[g][p + 2]);
            }
        }

        const float* bp  = bias + ((size_t)h * SEQ + r0 + gr) * SEQ + j * 128;
        const float* bp8 = bp + (size_t)8 * SEQ;
        uint32_t P2[16][2];
        #pragma unroll
        for (int n8 = 0; n8 < 16; n8++) {
            const int cc = n8 * 8 + 2 * tc;
            const float2 b01 = *(const float2*)(bp + cc);
            const float2 b23 = *(const float2*)(bp8 + cc);
            P2[n8][0] = exp2h2(fmaf(b01.x, LOG2E, S[n8][0]),
                               fmaf(b01.y, LOG2E, S[n8][1]));
            P2[n8][1] = exp2h2(fmaf(b23.x, LOG2E, S[n8][2]),
                               fmaf(b23.y, LOG2E, S[n8][3]));
        }

        #pragma unroll
        for (int kp = 0; kp < 8; kp++) {
            uint32_t aP[4];
            aP[0] = P2[2*kp    ][0];
            aP[1] = P2[2*kp    ][1];
            aP[2] = P2[2*kp + 1][0];
            aP[3] = P2[2*kp + 1][1];
            uint32_t bV[9][4];
            #pragma unroll
            for (int nt = 0; nt < 9; nt++)
                ldm4(bV[nt], vb + (nt * 16 + lrow) * FSTRIDE + kp * 32 + lchk * 16);
            #pragma unroll
            for (int n8 = 0; n8 < 17; n8++) {
                const int g = n8 >> 1, p = n8 & 1;
                mma16816(Oacc[n8], aP, bV[g][p], bV[g][p + 2]);
            }
        }
    }

    const float rs0 = __shfl_sync(0xffffffffu, Oacc[16][0], lane & 28);
    const float rs1 = __shfl_sync(0xffffffffu, Oacc[16][2], lane & 28);
    const float i0 = 1.f / rs0, i1 = 1.f / rs1;

    const size_t orow0 = (size_t)(b * SEQ + r0 + gr    ) * ldo + h * DH;
    const size_t orow1 = (size_t)(b * SEQ + r0 + gr + 8) * ldo + h * DH;
    #pragma unroll
    for (int n8 = 0; n8 < 16; n8++) {
        const int cc = n8 * 8 + 2 * tc;
        *(uint32_t*)(at + orow0 + cc) = pack2(Oacc[n8][0] * i0, Oacc[n8][1] * i0);
        *(uint32_t*)(at + orow1 + cc) = pack2(Oacc[n8][2] * i1, Oacc[n8][3] * i1);
    }
}

// ---------------- RMSNorm -> fp16 ----------------
__global__ __launch_bounds__(256) void rmsnorm_kernel(
    const float* __restrict__ x, const float* __restrict__ gamma,
    __half* __restrict__ xn)
{
    const size_t row = blockIdx.x;
    const float* xr = x + row * DIMC;
    const int t = threadIdx.x;

    float s = 0.f;
    for (int c = t; c < DIMC; c += 256) { float v = xr[c]; s += v * v; }
    __shared__ float red[8];
    #pragma unroll
    for (int o = 16; o; o >>= 1) s += __shfl_xor_sync(0xffffffffu, s, o);
    if ((t & 31) == 0) red[t >> 5] = s;
    __syncthreads();
    float tot = red[0]+red[1]+red[2]+red[3]+red[4]+red[5]+red[6]+red[7];
    float inv = rsqrtf(tot + 1e-5f) * RMS_SCALE;

    for (int c = t; c < DIMC; c += 256)
        xn[row * DIMC + c] = __float2half_rn(xr[c] * inv * gamma[c]);
}

// ---------------- merged weight-prep kernels ----------------
// wiT build (permuted). z=0: qkv cols 0..2303; z=1: ff; z=2: gate.
__global__ void prep_wiT_kernel(const float* __restrict__ wi, __half* __restrict__ wiT)
{
    int colBase, rowBase, rowMul;
    if (blockIdx.z == 0) {
        if (blockIdx.x >= 72) return;          // 2304/32
        colBase = 0; rowBase = 0; rowMul = 1;
    } else if (blockIdx.z == 1) {
        colBase = 2304; rowBase = 2304; rowMul = 2;
    } else {
        colBase = 10496; rowBase = 2305; rowMul = 2;
    }
    __shared__ float t[32][33];
    const int cx = colBase + blockIdx.x * 32 + threadIdx.x;
    const int ry = blockIdx.y * 32;
    #pragma unroll
    for (int j = 0; j < 32; j += 8)
        t[threadIdx.y + j][threadIdx.x] = wi[(size_t)(ry + threadIdx.y + j) * NPROJ + cx];
    __syncthreads();
    const int colRel0 = blockIdx.x * 32;
    const int dc = ry + threadIdx.x;
    #pragma unroll
    for (int j = 0; j < 32; j += 8) {
        const size_t drow = (size_t)rowBase + (size_t)rowMul * (colRel0 + threadIdx.y + j);
        wiT[drow * DIMC + dc] = __float2half_rn(t[threadIdx.x][threadIdx.y + j]);
    }
}

// wcat build: z=0: attn_wo -> wcat[col][row]; z=1: ff_wo -> wcat[col][2048+row]
__global__ void prep_wcat_kernel(const float* __restrict__ attn_wo,
                                 const float* __restrict__ ff_wo,
                                 __half* __restrict__ wcat)
{
    const float* src;
    int colOff;
    if (blockIdx.z == 0) {
        if (blockIdx.y >= 64) return;          // 2048/32 source rows
        src = attn_wo; colOff = 0;
    } else {
        src = ff_wo; colOff = 2048;
    }
    __shared__ float t[32][33];
    const int cx = blockIdx.x * 32 + threadIdx.x;  // src col (out dim), 0..2047
    const int ry = blockIdx.y * 32;                // src row (k dim)
    #pragma unroll
    for (int j = 0; j < 32; j += 8)
        t[threadIdx.y + j][threadIdx.x] = src[(size_t)(ry + threadIdx.y + j) * DIMC + cx];
    __syncthreads();
    const int dr0 = blockIdx.x * 32;
    const int dc  = ry + threadIdx.x;
    #pragma unroll
    for (int j = 0; j < 32; j += 8) {
        const size_t drow = (size_t)(dr0 + threadIdx.y + j);
        wcat[drow * NCAT + colOff + dc] = __float2half_rn(t[threadIdx.x][threadIdx.y + j]);
    }
}

// ---------------- launch ----------------
extern "C" void kernel_launch(void* const* d_in, const int* in_sizes, int n_in,
                              void* d_out, int out_size)
{
    const float *x = 0, *bias = 0, *gamma = 0, *wi = 0, *attn_wo = 0, *ff_wo = 0;
    for (int i = 0; i < n_in; i++) {
        switch (in_sizes[i]) {
            case  8388608: x       = (const float*)d_in[i]; break;
            case 67108864: bias    = (const float*)d_in[i]; break;
            case     2048: gamma   = (const float*)d_in[i]; break;
            case 38273024: wi      = (const float*)d_in[i]; break;
            case  4194304: attn_wo = (const float*)d_in[i]; break;
            case 16777216: ff_wo   = (const float*)d_in[i]; break;
        }
    }
    float* out = (float*)d_out;

    __half *xn, *wiT, *qt, *kt, *vt, *cat, *wcat;
    cudaGetSymbolAddress((void**)&xn,   g_xn);
    cudaGetSymbolAddress((void**)&wiT,  g_wiT);
    cudaGetSymbolAddress((void**)&qt,   g_qt);
    cudaGetSymbolAddress((void**)&kt,   g_kt);
    cudaGetSymbolAddress((void**)&vt,   g_vt);
    cudaGetSymbolAddress((void**)&cat,  g_cat);
    cudaGetSymbolAddress((void**)&wcat, g_wcat);

    cudaFuncSetAttribute(gemm_kernel,
                         cudaFuncAttributeMaxDynamicSharedMemorySize, SMEM_GEMM);
    cudaFuncSetAttribute(proj_kernel,
                         cudaFuncAttributeMaxDynamicSharedMemorySize, SMEM_GEMM);
    cudaFuncSetAttribute(flash_kernel,
                         cudaFuncAttributeMaxDynamicSharedMemorySize, SMEM_FLASH);

    // ---- fork side streams off the capture (default) stream via events ----
    cudaStream_t s1, s2;
    cudaStreamCreateWithFlags(&s1, cudaStreamNonBlocking);
    cudaStreamCreateWithFlags(&s2, cudaStreamNonBlocking);
    cudaEvent_t eFork, eWiT, eWcat;
    cudaEventCreateWithFlags(&eFork, cudaEventDisableTiming);
    cudaEventCreateWithFlags(&eWiT,  cudaEventDisableTiming);
    cudaEventCreateWithFlags(&eWcat, cudaEventDisableTiming);

    cudaEventRecord(eFork, 0);
    cudaStreamWaitEvent(s1, eFork, 0);
    cudaStreamWaitEvent(s2, eFork, 0);

    prep_wiT_kernel<<<dim3(256, DIMC/32, 3), dim3(32, 8), 0, s1>>>(wi, wiT);
    cudaEventRecord(eWiT, s1);
    prep_wcat_kernel<<<dim3(DIMC/32, FFI/32, 2), dim3(32, 8), 0, s2>>>(attn_wo, ff_wo, wcat);
    cudaEventRecord(eWcat, s2);

    rmsnorm_kernel<<<NROWS, 256>>>(x, gamma, xn);
    cudaStreamWaitEvent(0, eWiT, 0);

    // proj GEMM with fused gather/swiglu epilogue  (tile 128x64)
    proj_kernel<<<dim3(NROWS/128, NPROJ/64), 256, SMEM_GEMM>>>(
        xn, DIMC, wiT, DIMC, qt, kt, vt, cat, DIMC);

    // fused attention -> cat cols 0..2047
    flash_kernel<<<dim3(SEQ/128, BATCH*HEADS), 256, SMEM_FLASH>>>(
        qt, kt, vt, bias, cat, NCAT);

    cudaStreamWaitEvent(0, eWcat, 0);

    // out = cat @ wcat^T (K = 10240, tile 128x64)
    gemm_kernel<<<dim3(NROWS/128, DIMC/64), 256, SMEM_GEMM>>>(
        cat, NCAT, wcat, NCAT, out, DIMC, NCAT);

    cudaEventDestroy(eFork);
    cudaEventDestroy(eWiT);
    cudaEventDestroy(eWcat);
    cudaStreamDestroy(s1);
    cudaStreamDestroy(s2);
}

// round 17
// speedup vs baseline: 1.1017x; 1.1017x over previous
#include <cuda_runtime.h>
#include <cuda_fp16.h>
#include <math.h>
#include <stdint.h>

// ---------------- problem constants ----------------
#define DIMC   2048
#define SEQ    2048
#define BATCH  2
#define HEADS  16
#define DH     128
#define FFI    8192
#define NPROJ  18688            // 2048+128+128+8192+8192
#define NROWS  4096             // BATCH*SEQ
#define NCAT   10240            // 2048 (attn) + 8192 (ff)
#define RMS_SCALE 45.25483399593904f   // sqrt(2048)
#define Q_SCALE   0.08838834764831845f // 1/sqrt(128)
#define LOG2E     1.4426950408889634f

// gemm smem: 3 stages * 2 tiles * (128 rows * 144B) = 110592   (K-chunk = 64)
#define TILE_B   18432
#define STAGE_B  36864
#define SMEM_GEMM 110592
// flash smem: 2 stages * (K 128x272 + V 144x272) = 147968
#define FSTRIDE  272
#define FK_TILE  34816
#define FSTAGE   73984
#define SMEM_FLASH 147968

// ---------------- scratch (device globals; allocation-free) ----------------
__device__ __half g_xn  [(size_t)NROWS * DIMC];
__device__ __half g_wiT [(size_t)NPROJ * DIMC];     // PERMUTED: q|k|v|ff/gate interleaved
__device__ __half g_qt  [(size_t)BATCH * HEADS * SEQ * DH];
__device__ __half g_kt  [(size_t)BATCH * SEQ * DH];
__device__ __half g_vt  [(size_t)BATCH * DH * SEQ];
__device__ __half g_cat [(size_t)NROWS * NCAT];     // [at | h]
__device__ __half g_wcat[(size_t)DIMC * NCAT];      // [awT | fwT]

// ---------------- helpers ----------------
__device__ __forceinline__ uint32_t smem_u32(const void* p) {
    uint32_t a;
    asm("{ .reg .u64 t; cvta.to.shared.u64 t, %1; cvt.u32.u64 %0, t; }"
        : "=r"(a) : "l"(p));
    return a;
}
__device__ __forceinline__ void ldm4(uint32_t* r, uint32_t a) {
    asm volatile("ldmatrix.sync.aligned.m8n8.x4.shared.b16 {%0,%1,%2,%3}, [%4];"
                 : "=r"(r[0]), "=r"(r[1]), "=r"(r[2]), "=r"(r[3]) : "r"(a));
}
__device__ __forceinline__ void mma16816(float* d, const uint32_t* a,
                                         uint32_t b0, uint32_t b1) {
    asm volatile(
        "mma.sync.aligned.m16n8k16.row.col.f32.f16.f16.f32 "
        "{%0,%1,%2,%3}, {%4,%5,%6,%7}, {%8,%9}, {%0,%1,%2,%3};"
        : "+f"(d[0]), "+f"(d[1]), "+f"(d[2]), "+f"(d[3])
        : "r"(a[0]), "r"(a[1]), "r"(a[2]), "r"(a[3]), "r"(b0), "r"(b1));
}
__device__ __forceinline__ void cp16(uint32_t s, const void* g) {
    asm volatile("cp.async.cg.shared.global [%0], [%1], 16;" :: "r"(s), "l"(g));
}
#define CP_COMMIT() asm volatile("cp.async.commit_group;")
#define CP_WAITG1() asm volatile("cp.async.wait_group 1;" ::: "memory")
__device__ __forceinline__ uint32_t pack2(float v0, float v1) {
    __half2 H = __floats2half2_rn(v0, v1);
    return *(uint32_t*)&H;
}
__device__ __forceinline__ uint32_t exp2h2(float v0, float v1) {
    uint32_t p = pack2(v0, v1), r;
    asm("ex2.approx.f16x2 %0, %1;" : "=r"(r) : "r"(p));
    return r;
}

// ====== GEMM mainloop: K-chunk 64, 3-stage cp.async, ONE sync per chunk ======
#define GEMM_ISSUE(cidx, Aptr, lda_, Bptr, ldb_)                                        \
    {                                                                                   \
        const int k0i = (cidx) << 6;                                                    \
        const uint32_t db = sb + ((cidx) % 3) * STAGE_B;                                \
        _Pragma("unroll")                                                               \
        for (int qq = 0; qq < 4; qq++) {                                                \
            const int lin = qq * 256 + tid;                                             \
            const int rr = lin >> 3, ss = lin & 7;                                      \
            cp16(db + rr*144 + ss*16,                                                   \
                 (Aptr) + (size_t)(row0 + rr) * (lda_) + k0i + ss*8);                   \
            cp16(db + TILE_B + rr*144 + ss*16,                                          \
                 (Bptr) + (size_t)(col0 + rr) * (ldb_) + k0i + ss*8);                   \
        }                                                                               \
    }

#define GEMM_MAIN(Aptr, lda_, Bptr, ldb_, Kdim)                                         \
    float acc[2][8][4];                                                                 \
    _Pragma("unroll")                                                                   \
    for (int i = 0; i < 2; i++)                                                         \
        _Pragma("unroll")                                                               \
        for (int j = 0; j < 8; j++)                                                     \
            _Pragma("unroll")                                                           \
            for (int k = 0; k < 4; k++) acc[i][j][k] = 0.f;                             \
    const int NC = (Kdim) >> 6;                                                         \
    const int lrow = lane & 15;                                                         \
    const int lchk = lane >> 4;                                                         \
    GEMM_ISSUE(0, Aptr, lda_, Bptr, ldb_); CP_COMMIT();                                 \
    GEMM_ISSUE(1, Aptr, lda_, Bptr, ldb_); CP_COMMIT();                                 \
    for (int c = 0; c < NC; c++) {                                                      \
        CP_WAITG1();                       /* chunk c resident */                       \
        __syncthreads();                   /* prev compute drained */                   \
        if (c + 2 < NC) GEMM_ISSUE(c + 2, Aptr, lda_, Bptr, ldb_);                      \
        CP_COMMIT();                                                                    \
        const uint32_t tb = sb + (c % 3) * STAGE_B;                                     \
        _Pragma("unroll")                                                               \
        for (int kk = 0; kk < 4; kk++) {                                                \
            const int ch0 = kk * 2;                                                     \
            uint32_t aF[2][4], bF[4][4];                                                \
            _Pragma("unroll")                                                           \
            for (int mt = 0; mt < 2; mt++)                                              \
                ldm4(aF[mt], tb + (mw*32 + mt*16 + lrow)*144 + (ch0 + lchk)*16);        \
            _Pragma("unroll")                                                           \
            for (int nt = 0; nt < 4; nt++)                                              \
                ldm4(bF[nt], tb + TILE_B + (nw*64 + nt*16 + lrow)*144 + (ch0 + lchk)*16);\
            _Pragma("unroll")                                                           \
            for (int mt = 0; mt < 2; mt++) {                                            \
                _Pragma("unroll")                                                       \
                for (int n8 = 0; n8 < 8; n8++) {                                        \
                    const int g = n8 >> 1, p = n8 & 1;                                  \
                    mma16816(acc[mt][n8], aF[mt], bF[g][p], bF[g][p + 2]);              \
                }                                                                       \
            }                                                                           \
        }                                                                               \
    }

// ---------------- plain GEMM (final output, optional accumulate) -----------
__global__ __launch_bounds__(256, 2) void gemm_kernel(
    const __half* __restrict__ A, int lda,
    const __half* __restrict__ B, int ldb,
    float* __restrict__ C, int ldc, int accum, int K)
{
    extern __shared__ char smem[];
    const uint32_t sb = smem_u32(smem);
    const int tid  = threadIdx.x;
    const int wid  = tid >> 5;
    const int lane = tid & 31;
    const int mw   = wid & 3;
    const int nw   = wid >> 2;
    const int row0 = blockIdx.x * 128, col0 = blockIdx.y * 128;

    GEMM_MAIN(A, lda, B, ldb, K)

    const int tr  = lane >> 2;
    const int tc2 = (lane & 3) * 2;
    #pragma unroll
    for (int mt = 0; mt < 2; mt++)
        #pragma unroll
        for (int hf = 0; hf < 2; hf++) {
            const int r = row0 + mw*32 + mt*16 + hf*8 + tr;
            #pragma unroll
            for (int n8 = 0; n8 < 8; n8++) {
                const int cc = col0 + nw*64 + n8*8 + tc2;
                float* cp = C + (size_t)r * ldc + cc;
                if (accum) {
                    cp[0] += acc[mt][n8][hf*2 + 0];
                    cp[1] += acc[mt][n8][hf*2 + 1];
                } else {
                    cp[0] = acc[mt][n8][hf*2 + 0];
                    cp[1] = acc[mt][n8][hf*2 + 1];
                }
            }
        }
}

// ---------------- proj GEMM with fused gather epilogue ----------------
// B = permuted wiT: rows 0..2047 q, 2048..2175 k, 2176..2303 v,
//                   2304..18687 interleaved (even=ff_j, odd=gate_j).
__global__ __launch_bounds__(256, 2) void proj_kernel(
    const __half* __restrict__ A, int lda,
    const __half* __restrict__ B, int ldb,
    __half* __restrict__ q, __half* __restrict__ kmat,
    __half* __restrict__ vmat, __half* __restrict__ cat, int K)
{
    extern __shared__ char smem[];
    const uint32_t sb = smem_u32(smem);
    const int tid  = threadIdx.x;
    const int wid  = tid >> 5;
    const int lane = tid & 31;
    const int mw   = wid & 3;
    const int nw   = wid >> 2;
    const int row0 = blockIdx.x * 128, col0 = blockIdx.y * 128;

    GEMM_MAIN(A, lda, B, ldb, K)

    const int tr  = lane >> 2;
    const int tc2 = (lane & 3) * 2;

    #pragma unroll
    for (int mt = 0; mt < 2; mt++)
        #pragma unroll
        for (int hf = 0; hf < 2; hf++) {
            const int r = row0 + mw*32 + mt*16 + hf*8 + tr;
            const int i = r & 2047, b = r >> 11;
            #pragma unroll
            for (int n8 = 0; n8 < 8; n8++) {
                const int cc = col0 + nw*64 + n8*8 + tc2;
                const float v0 = acc[mt][n8][hf*2 + 0];
                const float v1 = acc[mt][n8][hf*2 + 1];
                if (col0 < 2048) {
                    // q[z][i][d], pre-scaled by Q_SCALE*LOG2E
                    const int h = cc >> 7, d = cc & 127;
                    const size_t o = ((size_t)(b * HEADS + h) * SEQ + i) * DH + d;
                    *(uint32_t*)(q + o) = pack2(v0 * (Q_SCALE * LOG2E),
                                                v1 * (Q_SCALE * LOG2E));
                } else if (col0 == 2048) {
                    // k[b][j][d]
                    const int d = cc - 2048;
                    *(uint32_t*)(kmat + (size_t)r * DH + d) = pack2(v0, v1);
                } else if (col0 == 2176) {
                    // v[b][d][j]: scattered transpose (small region)
                    const int d = cc - 2176;
                    const size_t o = (size_t)b * DH * SEQ + (size_t)d * SEQ + i;
                    vmat[o]       = __float2half_rn(v0);
                    vmat[o + SEQ] = __float2half_rn(v1);
                } else {
                    // interleaved ff/gate: v0 = ff_j, v1 = gate_j
                    const int jp = (cc - 2304) >> 1;
                    const float sw = v1 / (1.f + __expf(-v1));
                    cat[(size_t)r * NCAT + 2048 + jp] = __float2half_rn(v0 * sw);
                }
            }
        }
}

// ---------------- fused flash attention ----------------
__global__ __launch_bounds__(256) void flash_kernel(
    const __half* __restrict__ q,      // [z][i][dh]  (pre-scaled by Q_SCALE*log2e)
    const __half* __restrict__ kmat,   // [b][key][dh]
    const __half* __restrict__ vmat,   // [b][dh][key]
    const float* __restrict__ bias,    // [h][i][j]
    __half* __restrict__ at, int ldo)
{
    extern __shared__ char smem[];
    const uint32_t sb = smem_u32(smem);
    const int tid  = threadIdx.x;
    const int wid  = tid >> 5;
    const int lane = tid & 31;
    const int gr   = lane >> 2;
    const int tc   = lane & 3;
    const int lrow = lane & 15;
    const int lchk = lane >> 4;

    const int z = blockIdx.y, b = z >> 4, h = z & 15;
    const int r0 = blockIdx.x * 128 + wid * 16;

    // init ones-row (dh=128) and zero rows of both V buffers
    #pragma unroll
    for (int bufi = 0; bufi < 2; bufi++) {
        char* vrows = smem + bufi * FSTAGE + FK_TILE + 128 * FSTRIDE;
        for (int i = tid; i < 16 * 136; i += 256) {
            const int r = i / 136, cc = i % 136;
            *(__half*)(vrows + r * FSTRIDE + cc * 2) =
                (r == 0) ? __float2half(1.0f) : __float2half(0.0f);
        }
    }

    uint32_t qF[8][4];
    {
        const __half* qb = q + (size_t)z * SEQ * DH;
        #pragma unroll
        for (int kt = 0; kt < 8; kt++) {
            const int c0 = kt * 16 + 2 * tc;
            qF[kt][0] = *(const uint32_t*)(qb + (size_t)(r0 + gr    ) * DH + c0);
            qF[kt][1] = *(const uint32_t*)(qb + (size_t)(r0 + gr + 8) * DH + c0);
            qF[kt][2] = *(const uint32_t*)(qb + (size_t)(r0 + gr    ) * DH + c0 + 8);
            qF[kt][3] = *(const uint32_t*)(qb + (size_t)(r0 + gr + 8) * DH + c0 + 8);
        }
    }

    const __half* ksrc = kmat + (size_t)b * SEQ * DH;
    const __half* vsrc = vmat + (size_t)b * DH * SEQ;

    auto issueKV = [&](int j, int buf) {
        const uint32_t kb = sb + buf * FSTAGE;
        #pragma unroll
        for (int t = 0; t < 8; t++) {
            const int lin = t * 256 + tid;
            const int r = lin >> 4, s = lin & 15;
            cp16(kb + r * FSTRIDE + s * 16,
                 ksrc + (size_t)(j * 128 + r) * DH + s * 8);
            cp16(kb + FK_TILE + r * FSTRIDE + s * 16,
                 vsrc + (size_t)r * SEQ + j * 128 + s * 8);
        }
    };

    issueKV(0, 0);
    CP_COMMIT();

    float Oacc[17][4];
    #pragma unroll
    for (int i = 0; i < 17; i++)
        #pragma unroll
        for (int k = 0; k < 4; k++) Oacc[i][k] = 0.f;

    for (int j = 0; j < 16; j++) {
        const int buf = j & 1;
        __syncthreads();
        if (j + 1 < 16) issueKV(j + 1, buf ^ 1);
        CP_COMMIT();
        CP_WAITG1();
        __syncthreads();

        const uint32_t kb = sb + buf * FSTAGE;
        const uint32_t vb = kb + FK_TILE;

        float S[16][4];
        #pragma unroll
        for (int i = 0; i < 16; i++)
            #pragma unroll
            for (int k = 0; k < 4; k++) S[i][k] = 0.f;

        #pragma unroll
        for (int kt = 0; kt < 8; kt++) {
            uint32_t bK[8][4];
            #pragma unroll
            for (int nt = 0; nt < 8; nt++)
                ldm4(bK[nt], kb + (nt * 16 + lrow) * FSTRIDE + kt * 32 + lchk * 16);
            #pragma unroll
            for (int n8 = 0; n8 < 16; n8++) {
                const int g = n8 >> 1, p = n8 & 1;
                mma16816(S[n8], qF[kt], bK[g][p], bK[g][p + 2]);
            }
        }

        const float* bp  = bias + ((size_t)h * SEQ + r0 + gr) * SEQ + j * 128;
        const float* bp8 = bp + (size_t)8 * SEQ;
        uint32_t P2[16][2];
        #pragma unroll
        for (int n8 = 0; n8 < 16; n8++) {
            const int cc = n8 * 8 + 2 * tc;
            const float2 b01 = *(const float2*)(bp + cc);
            const float2 b23 = *(const float2*)(bp8 + cc);
            P2[n8][0] = exp2h2(fmaf(b01.x, LOG2E, S[n8][0]),
                               fmaf(b01.y, LOG2E, S[n8][1]));
            P2[n8][1] = exp2h2(fmaf(b23.x, LOG2E, S[n8][2]),
                               fmaf(b23.y, LOG2E, S[n8][3]));
        }

        #pragma unroll
        for (int kp = 0; kp < 8; kp++) {
            uint32_t aP[4];
            aP[0] = P2[2*kp    ][0];
            aP[1] = P2[2*kp    ][1];
            aP[2] = P2[2*kp + 1][0];
            aP[3] = P2[2*kp + 1][1];
            uint32_t bV[9][4];
            #pragma unroll
            for (int nt = 0; nt < 9; nt++)
                ldm4(bV[nt], vb + (nt * 16 + lrow) * FSTRIDE + kp * 32 + lchk * 16);
            #pragma unroll
            for (int n8 = 0; n8 < 17; n8++) {
                const int g = n8 >> 1, p = n8 & 1;
                mma16816(Oacc[n8], aP, bV[g][p], bV[g][p + 2]);
            }
        }
    }

    const float rs0 = __shfl_sync(0xffffffffu, Oacc[16][0], lane & 28);
    const float rs1 = __shfl_sync(0xffffffffu, Oacc[16][2], lane & 28);
    const float i0 = 1.f / rs0, i1 = 1.f / rs1;

    const size_t orow0 = (size_t)(b * SEQ + r0 + gr    ) * ldo + h * DH;
    const size_t orow1 = (size_t)(b * SEQ + r0 + gr + 8) * ldo + h * DH;
    #pragma unroll
    for (int n8 = 0; n8 < 16; n8++) {
        const int cc = n8 * 8 + 2 * tc;
        *(uint32_t*)(at + orow0 + cc) = pack2(Oacc[n8][0] * i0, Oacc[n8][1] * i0);
        *(uint32_t*)(at + orow1 + cc) = pack2(Oacc[n8][2] * i1, Oacc[n8][3] * i1);
    }
}

// ---------------- RMSNorm -> fp16 ----------------
__global__ __launch_bounds__(256) void rmsnorm_kernel(
    const float* __restrict__ x, const float* __restrict__ gamma,
    __half* __restrict__ xn)
{
    const size_t row = blockIdx.x;
    const float* xr = x + row * DIMC;
    const int t = threadIdx.x;

    float s = 0.f;
    for (int c = t; c < DIMC; c += 256) { float v = xr[c]; s += v * v; }
    __shared__ float red[8];
    #pragma unroll
    for (int o = 16; o; o >>= 1) s += __shfl_xor_sync(0xffffffffu, s, o);
    if ((t & 31) == 0) red[t >> 5] = s;
    __syncthreads();
    float tot = red[0]+red[1]+red[2]+red[3]+red[4]+red[5]+red[6]+red[7];
    float inv = rsqrtf(tot + 1e-5f) * RMS_SCALE;

    for (int c = t; c < DIMC; c += 256)
        xn[row * DIMC + c] = __float2half_rn(xr[c] * inv * gamma[c]);
}

// ---------------- merged weight-prep kernels ----------------
__global__ void prep_wiT_kernel(const float* __restrict__ wi, __half* __restrict__ wiT)
{
    int colBase, rowBase, rowMul;
    if (blockIdx.z == 0) {
        if (blockIdx.x >= 72) return;          // 2304/32
        colBase = 0; rowBase = 0; rowMul = 1;
    } else if (blockIdx.z == 1) {
        colBase = 2304; rowBase = 2304; rowMul = 2;
    } else {
        colBase = 10496; rowBase = 2305; rowMul = 2;
    }
    __shared__ float t[32][33];
    const int cx = colBase + blockIdx.x * 32 + threadIdx.x;
    const int ry = blockIdx.y * 32;
    #pragma unroll
    for (int j = 0; j < 32; j += 8)
        t[threadIdx.y + j][threadIdx.x] = wi[(size_t)(ry + threadIdx.y + j) * NPROJ + cx];
    __syncthreads();
    const int colRel0 = blockIdx.x * 32;
    const int dc = ry + threadIdx.x;
    #pragma unroll
    for (int j = 0; j < 32; j += 8) {
        const size_t drow = (size_t)rowBase + (size_t)rowMul * (colRel0 + threadIdx.y + j);
        wiT[drow * DIMC + dc] = __float2half_rn(t[threadIdx.x][threadIdx.y + j]);
    }
}

__global__ void prep_wcat_kernel(const float* __restrict__ attn_wo,
                                 const float* __restrict__ ff_wo,
                                 __half* __restrict__ wcat)
{
    const float* src;
    int colOff;
    if (blockIdx.z == 0) {
        if (blockIdx.y >= 64) return;          // 2048/32 source rows
        src = attn_wo; colOff = 0;
    } else {
        src = ff_wo; colOff = 2048;
    }
    __shared__ float t[32][33];
    const int cx = blockIdx.x * 32 + threadIdx.x;
    const int ry = blockIdx.y * 32;
    #pragma unroll
    for (int j = 0; j < 32; j += 8)
        t[threadIdx.y + j][threadIdx.x] = src[(size_t)(ry + threadIdx.y + j) * DIMC + cx];
    __syncthreads();
    const int dr0 = blockIdx.x * 32;
    const int dc  = ry + threadIdx.x;
    #pragma unroll
    for (int j = 0; j < 32; j += 8) {
        const size_t drow = (size_t)(dr0 + threadIdx.y + j);
        wcat[drow * NCAT + colOff + dc] = __float2half_rn(t[threadIdx.x][threadIdx.y + j]);
    }
}

// ---------------- launch ----------------
extern "C" void kernel_launch(void* const* d_in, const int* in_sizes, int n_in,
                              void* d_out, int out_size)
{
    const float *x = 0, *bias = 0, *gamma = 0, *wi = 0, *attn_wo = 0, *ff_wo = 0;
    for (int i = 0; i < n_in; i++) {
        switch (in_sizes[i]) {
            case  8388608: x       = (const float*)d_in[i]; break;
            case 67108864: bias    = (const float*)d_in[i]; break;
            case     2048: gamma   = (const float*)d_in[i]; break;
            case 38273024: wi      = (const float*)d_in[i]; break;
            case  4194304: attn_wo = (const float*)d_in[i]; break;
            case 16777216: ff_wo   = (const float*)d_in[i]; break;
        }
    }
    float* out = (float*)d_out;

    __half *xn, *wiT, *qt, *kt, *vt, *cat, *wcat;
    cudaGetSymbolAddress((void**)&xn,   g_xn);
    cudaGetSymbolAddress((void**)&wiT,  g_wiT);
    cudaGetSymbolAddress((void**)&qt,   g_qt);
    cudaGetSymbolAddress((void**)&kt,   g_kt);
    cudaGetSymbolAddress((void**)&vt,   g_vt);
    cudaGetSymbolAddress((void**)&cat,  g_cat);
    cudaGetSymbolAddress((void**)&wcat, g_wcat);

    cudaFuncSetAttribute(gemm_kernel,
                         cudaFuncAttributeMaxDynamicSharedMemorySize, SMEM_GEMM);
    cudaFuncSetAttribute(proj_kernel,
                         cudaFuncAttributeMaxDynamicSharedMemorySize, SMEM_GEMM);
    cudaFuncSetAttribute(flash_kernel,
                         cudaFuncAttributeMaxDynamicSharedMemorySize, SMEM_FLASH);

    // ---- streams/events ----
    cudaStream_t s1, s2;
    cudaStreamCreateWithFlags(&s1, cudaStreamNonBlocking);
    cudaStreamCreateWithFlags(&s2, cudaStreamNonBlocking);
    cudaEvent_t eFork, eWiT, eProj, eFF;
    cudaEventCreateWithFlags(&eFork, cudaEventDisableTiming);
    cudaEventCreateWithFlags(&eWiT,  cudaEventDisableTiming);
    cudaEventCreateWithFlags(&eProj, cudaEventDisableTiming);
    cudaEventCreateWithFlags(&eFF,   cudaEventDisableTiming);

    cudaEventRecord(eFork, 0);
    cudaStreamWaitEvent(s1, eFork, 0);
    cudaStreamWaitEvent(s2, eFork, 0);

    // s1: prep_wiT (needed by proj)   s2: prep_wcat (needed by out GEMMs)
    prep_wiT_kernel<<<dim3(256, DIMC/32, 3), dim3(32, 8), 0, s1>>>(wi, wiT);
    cudaEventRecord(eWiT, s1);
    prep_wcat_kernel<<<dim3(DIMC/32, FFI/32, 2), dim3(32, 8), 0, s2>>>(attn_wo, ff_wo, wcat);

    // main: rmsnorm overlaps preps, then proj
    rmsnorm_kernel<<<NROWS, 256>>>(x, gamma, xn);
    cudaStreamWaitEvent(0, eWiT, 0);
    proj_kernel<<<dim3(NROWS/128, NPROJ/128), 256, SMEM_GEMM>>>(
        xn, DIMC, wiT, DIMC, qt, kt, vt, cat, DIMC);
    cudaEventRecord(eProj, 0);

    // s2: ff-part of out GEMM (K = 8192, cols 2048.. of cat/wcat) — overlaps flash
    cudaStreamWaitEvent(s2, eProj, 0);
    gemm_kernel<<<dim3(NROWS/128, DIMC/128), 256, SMEM_GEMM, s2>>>(
        cat + 2048, NCAT, wcat + 2048, NCAT, out, DIMC, /*accum=*/0, FFI);
    cudaEventRecord(eFF, s2);

    // main: flash attention -> cat cols 0..2047
    flash_kernel<<<dim3(SEQ/128, BATCH*HEADS), 256, SMEM_FLASH>>>(
        qt, kt, vt, bias, cat, NCAT);

    // main: attn-part of out GEMM accumulates after flash + ff GEMM
    cudaStreamWaitEvent(0, eFF, 0);
    gemm_kernel<<<dim3(NROWS/128, DIMC/128), 256, SMEM_GEMM>>>(
        cat, NCAT, wcat, NCAT, out, DIMC, /*accum=*/1, 2048);

    cudaEventDestroy(eFork);
    cudaEventDestroy(eWiT);
    cudaEventDestroy(eProj);
    cudaEventDestroy(eFF);
    cudaStreamDestroy(s1);
    cudaStreamDestroy(s2);
}